// round 9
// baseline (speedup 1.0000x reference)
#include <cuda_runtime.h>
#include <math.h>

// Fixed shapes per reference
#define N_PTS 262144
#define B_ 4
#define T_ 4
#define P_ 512
#define R_ 256
#define C_ 64
#define H_ 512
#define W_ 512
#define HW_ (H_ * W_)
#define RC_ (R_ * C_)
#define PRC_ (P_ * RC_)

#define SCATTER_BLOCKS (N_PTS / 16)        // 16384: 16 points per 256-thr block
#define COPY_BLOCKS 16384
#define EPI_BLOCKS 512                     // B*H*C / 256 threads
#define SCRATCH_ELEMS (B_ * H_ * T_ * C_)  // 524288 floats (2MB, L2-resident)

// Privatized accumulator [b][y][t][c] (channel-contiguous -> coalesced REDs).
// BSS zero-init; epilogue re-zeros after consuming (invariant across replays).
__device__ float g_scratch[SCRATCH_ELEMS];
// Scatter-done counter + epilogue-done counter; self-resetting each launch.
__device__ unsigned int g_done;
__device__ unsigned int g_epi_done;

__device__ __forceinline__ void red_add_v4(float* p, float4 v) {
    asm volatile("red.global.add.v4.f32 [%0], {%1,%2,%3,%4};"
                 :: "l"(p), "f"(v.x), "f"(v.y), "f"(v.z), "f"(v.w)
                 : "memory");
}

// ONE kernel, three roles by blockIdx:
//   [0, SCATTER)                : gather + coalesced red.v4 into scratch,
//                                 then fence + count into g_done.
//   [SCATTER, SCATTER+COPY)     : stream out = spatial, SKIPPING the out4
//                                 quads with idx%128==0 (== out[b][c][y][0..3],
//                                 exactly the scatter footprint).
//   [SCATTER+COPY, +EPI)        : spin until g_done==SCATTER, then write the
//                                 skipped quads non-atomically:
//                                 out = spatial + scratch. Disjoint addresses
//                                 from the copy -> no race, no atomics on out.
// Scatter is front-loaded (lowest blockIdx) so it completes early; the
// epilogue then runs hidden under the copy's remaining streaming waves.
__global__ void __launch_bounds__(256) pp_mega_kernel(
    const int4*  __restrict__ coords,
    const float* __restrict__ pview,
    const float4* __restrict__ spatial4,
    float4* __restrict__ out4)
{
    const int tid = threadIdx.x;
    const unsigned bid = blockIdx.x;

    if (bid < SCATTER_BLOCKS) {
        // ---------------- scatter path ----------------
        const int warp   = tid >> 5;
        const int half   = (tid >> 4) & 1;
        const int lane16 = tid & 15;
        const int pt = bid * 16 + warp * 2 + half;

        int4 c = coords[pt];
        const int b = c.x, t = c.y, yy = c.z, xx = c.w;

        // Replicate reference f32 math exactly (no FMA contraction) so the
        // xf==0 special case matches bit-for-bit.
        float yf = __fadd_rn(__fmul_rn((float)yy, 0.2f), -51.2f);
        float xf = __fadd_rn(__fmul_rn((float)xx, 0.2f), -51.2f);

        float r = sqrtf(__fadd_rn(__fmul_rn(xf, xf), __fmul_rn(yf, yf)));
        float psi;
        if (xf == 0.0f && yf >= 0.0f) {
            psi = 1.57079632679489662f;   // pi/2
        } else {
            psi = atan2f(yf, xf);
        }

        float r_idx = __fdiv_rn(r, 0.3f);
        float p_idx = __fdiv_rn(__fadd_rn(psi, 3.14159265358979323846f),
                                0.012566370614359172f);

        int r0i = (int)floorf(r_idx);
        int p0i = (int)floorf(p_idx);
        // t frac is exactly 0 -> t+1 corner weight == 0, skipped.

        const float fr = r_idx - (float)r0i;
        const float fp = p_idx - (float)p0i;

        const int r0 = r0i * C_;
        const int r1 = min(r0i + 1, R_ - 1) * C_;
        const int p0 = p0i * RC_;
        const int p1 = min(p0i + 1, P_ - 1) * RC_;

        const float* base = pview + (b * T_ + t) * PRC_ + 4 * lane16;

        float4 v00 = *(const float4*)(base + p0 + r0);
        float4 v01 = *(const float4*)(base + p0 + r1);
        float4 v10 = *(const float4*)(base + p1 + r0);
        float4 v11 = *(const float4*)(base + p1 + r1);

        const float wr0 = 1.0f - fr, wr1 = fr;
        const float wp0 = 1.0f - fp, wp1 = fp;

        float4 acc;
        acc.x = wp0 * (wr0 * v00.x + wr1 * v01.x) + wp1 * (wr0 * v10.x + wr1 * v11.x);
        acc.y = wp0 * (wr0 * v00.y + wr1 * v01.y) + wp1 * (wr0 * v10.y + wr1 * v11.y);
        acc.z = wp0 * (wr0 * v00.z + wr1 * v01.z) + wp1 * (wr0 * v10.z + wr1 * v11.z);
        acc.w = wp0 * (wr0 * v00.w + wr1 * v01.w) + wp1 * (wr0 * v10.w + wr1 * v11.w);

        float* dst = g_scratch + ((b * H_ + yy) * T_ + t) * C_ + 4 * lane16;
        red_add_v4(dst, acc);

        // Publish: my reds are ordered before the counter bump.
        __threadfence();
        __syncthreads();
        if (tid == 0) atomicAdd(&g_done, 1u);
        return;
    }

    if (bid < SCATTER_BLOCKS + COPY_BLOCKS) {
        // ---------------- copy path (skips the scatter footprint) ----------
        int idx = (bid - SCATTER_BLOCKS) * 256 + tid;
        const int stride = COPY_BLOCKS * 256;          // 4194304
        #pragma unroll
        for (int i = 0; i < 4; i++) {
            if ((idx & 127) != 0)                      // hole: out[b][c][y][0..3]
                out4[idx] = spatial4[idx];
            idx += stride;
        }
        return;
    }

    // ---------------- epilogue path (in-grid, overlapped with copy) --------
    // Wait until every scatter block has published its reds.
    if (tid == 0) {
        while (*(volatile unsigned int*)&g_done < SCATTER_BLOCKS)
            __nanosleep(128);
    }
    __syncthreads();
    __threadfence();   // acquire: scratch reds now visible

    const int idx = (bid - SCATTER_BLOCKS - COPY_BLOCKS) * 256 + tid; // (b,y,c)
    const int ch = idx & (C_ - 1);
    const int y  = (idx >> 6) & (H_ - 1);
    const int b  = idx >> 15;

    const int sbase = ((b * H_ + y) * T_) * C_ + ch;   // t stride = C_
    float v0 = g_scratch[sbase];
    float v1 = g_scratch[sbase + C_];
    float v2 = g_scratch[sbase + 2 * C_];
    float v3 = g_scratch[sbase + 3 * C_];

    g_scratch[sbase]          = 0.0f;                  // re-zero for next replay
    g_scratch[sbase + C_]     = 0.0f;
    g_scratch[sbase + 2 * C_] = 0.0f;
    g_scratch[sbase + 3 * C_] = 0.0f;

    // The hole quad this thread owns: out4 index of out[b][ch][y][0..3]
    const int hole = (b * (C_ * HW_) + ch * HW_ + y * W_) >> 2;
    float4 s = spatial4[hole];
    s.x += v0; s.y += v1; s.z += v2; s.w += v3;
    out4[hole] = s;                                    // non-atomic, disjoint from copy

    // Self-reset counters: last epilogue block to finish zeroes them so every
    // graph replay starts from the same state.
    __syncthreads();
    if (tid == 0) {
        unsigned int prev = atomicAdd(&g_epi_done, 1u);
        if (prev == EPI_BLOCKS - 1) {
            g_done = 0u;
            g_epi_done = 0u;
            __threadfence();
        }
    }
}

extern "C" void kernel_launch(void* const* d_in, const int* in_sizes, int n_in,
                              void* d_out, int out_size) {
    const int*   coords  = (const int*)d_in[0];   // voxel_coords [N,4] int32
    const float* pview   = (const float*)d_in[1]; // [B,T,P,R,C] f32
    const float* spatial = (const float*)d_in[2]; // [B,C,H,W] f32
    float* out = (float*)d_out;

    pp_mega_kernel<<<SCATTER_BLOCKS + COPY_BLOCKS + EPI_BLOCKS, 256>>>(
        (const int4*)coords, pview, (const float4*)spatial, (float4*)out);
}

// round 10
// speedup vs baseline: 1.1465x; 1.1465x over previous
#include <cuda_runtime.h>
#include <math.h>

// Fixed shapes per reference
#define N_PTS 262144
#define B_ 4
#define T_ 4
#define P_ 512
#define R_ 256
#define C_ 64
#define H_ 512
#define W_ 512
#define HW_ (H_ * W_)
#define RC_ (R_ * C_)
#define PRC_ (P_ * RC_)

#define BLOCKS (N_PTS / 16)               // 16384 blocks of 256 threads
#define COPY_ITERS 4                      // 16384*256*4 = 16.7M float4 = 256MB
#define SCRATCH_ELEMS (B_ * H_ * T_ * C_) // 524288 floats (2MB, L2-resident)

// Privatized accumulator [b][y][t][c] (channel-contiguous -> coalesced REDs).
// BSS zero-init; epilogue re-zeros after consuming (invariant across replays).
__device__ float g_scratch[SCRATCH_ELEMS];

__device__ __forceinline__ void red_add_v4(float* p, float4 v) {
    asm volatile("red.global.add.v4.f32 [%0], {%1,%2,%3,%4};"
                 :: "l"(p), "f"(v.x), "f"(v.y), "f"(v.z), "f"(v.w)
                 : "memory");
}

// Every block does BOTH jobs: scatter 16 points AND copy 4 float4 per thread.
// This keeps streaming (DRAM-saturating) and gather (latency-bound) traffic
// co-resident on every SM for the whole kernel, instead of running as two
// sequential phases. The independent copy loads also hide the atan2->index
// dependency chain that precedes the gather loads.
__global__ void __launch_bounds__(256) pp_fused_kernel(
    const int4*  __restrict__ coords,
    const float* __restrict__ pview,
    const float4* __restrict__ spatial4,
    float4* __restrict__ out4)
{
    const int tid = threadIdx.x;
    const int bid = blockIdx.x;

    // ---- scatter setup: 16 lanes per point ----
    const int lane16 = tid & 15;
    const int pt = bid * 16 + (tid >> 4);

    int4 c = coords[pt];
    const int b = c.x, t = c.y, yy = c.z, xx = c.w;

    // Replicate reference f32 math exactly (no FMA contraction) so the
    // xf==0 special case matches bit-for-bit.
    float yf = __fadd_rn(__fmul_rn((float)yy, 0.2f), -51.2f);
    float xf = __fadd_rn(__fmul_rn((float)xx, 0.2f), -51.2f);

    float r = sqrtf(__fadd_rn(__fmul_rn(xf, xf), __fmul_rn(yf, yf)));
    float psi;
    if (xf == 0.0f && yf >= 0.0f) {
        psi = 1.57079632679489662f;       // pi/2
    } else {
        psi = atan2f(yf, xf);
    }

    float r_idx = __fdiv_rn(r, 0.3f);
    float p_idx = __fdiv_rn(__fadd_rn(psi, 3.14159265358979323846f),
                            0.012566370614359172f);

    int r0i = (int)floorf(r_idx);
    int p0i = (int)floorf(p_idx);
    // t frac is exactly 0 (integer cast to float) -> t+1 corner weight == 0.

    const float fr = r_idx - (float)r0i;
    const float fp = p_idx - (float)p0i;

    const int r0 = r0i * C_;
    const int r1 = min(r0i + 1, R_ - 1) * C_;
    const int p0 = p0i * RC_;
    const int p1 = min(p0i + 1, P_ - 1) * RC_;

    const float* base = pview + (b * T_ + t) * PRC_ + 4 * lane16;

    // Issue the 4 gather loads (long-latency, independent).
    float4 v00 = *(const float4*)(base + p0 + r0);
    float4 v01 = *(const float4*)(base + p0 + r1);
    float4 v10 = *(const float4*)(base + p1 + r0);
    float4 v11 = *(const float4*)(base + p1 + r1);

    // ---- copy slice: 4 quads per thread, grid-strided (fills gather latency)
    {
        int idx = bid * 256 + tid;
        const int stride = BLOCKS * 256;               // 4194304
        #pragma unroll
        for (int i = 0; i < COPY_ITERS; i++) {
            out4[idx] = spatial4[idx];
            idx += stride;
        }
    }

    // ---- interpolate + coalesced fire-and-forget red into scratch ----
    const float wr0 = 1.0f - fr, wr1 = fr;
    const float wp0 = 1.0f - fp, wp1 = fp;

    float4 acc;
    acc.x = wp0 * (wr0 * v00.x + wr1 * v01.x) + wp1 * (wr0 * v10.x + wr1 * v11.x);
    acc.y = wp0 * (wr0 * v00.y + wr1 * v01.y) + wp1 * (wr0 * v10.y + wr1 * v11.y);
    acc.z = wp0 * (wr0 * v00.z + wr1 * v01.z) + wp1 * (wr0 * v10.z + wr1 * v11.z);
    acc.w = wp0 * (wr0 * v00.w + wr1 * v01.w) + wp1 * (wr0 * v10.w + wr1 * v11.w);

    float* dst = g_scratch + ((b * H_ + yy) * T_ + t) * C_ + 4 * lane16;
    red_add_v4(dst, acc);
}

// Epilogue: one thread per (b, y, c) handles all 4 t values.
//  - scratch reads are L2-hot (just written by the scatter reds)
//  - scratch is zeroed back in place (keeps the no-memset invariant)
//  - out update is fire-and-forget red.v4 (no dependent DRAM read)
__global__ void __launch_bounds__(256) pp_add_kernel(float* __restrict__ out)
{
    const int idx = blockIdx.x * 256 + threadIdx.x;  // (b, y, c) flat
    const int ch = idx & (C_ - 1);
    const int y  = (idx >> 6) & (H_ - 1);
    const int b  = idx >> 15;

    const int sbase = ((b * H_ + y) * T_) * C_ + ch;   // t stride = C_
    float v0 = g_scratch[sbase];
    float v1 = g_scratch[sbase + C_];
    float v2 = g_scratch[sbase + 2 * C_];
    float v3 = g_scratch[sbase + 3 * C_];

    g_scratch[sbase]          = 0.0f;
    g_scratch[sbase + C_]     = 0.0f;
    g_scratch[sbase + 2 * C_] = 0.0f;
    g_scratch[sbase + 3 * C_] = 0.0f;

    float4 v = make_float4(v0, v1, v2, v3);
    // out[b][ch][y][0..3] — 16B-aligned (base is a multiple of 512 floats)
    red_add_v4(out + b * (C_ * HW_) + ch * HW_ + y * W_, v);
}

extern "C" void kernel_launch(void* const* d_in, const int* in_sizes, int n_in,
                              void* d_out, int out_size) {
    const int*   coords  = (const int*)d_in[0];   // voxel_coords [N,4] int32
    const float* pview   = (const float*)d_in[1]; // [B,T,P,R,C] f32
    const float* spatial = (const float*)d_in[2]; // [B,C,H,W] f32
    float* out = (float*)d_out;

    pp_fused_kernel<<<BLOCKS, 256>>>(
        (const int4*)coords, pview, (const float4*)spatial, (float4*)out);

    pp_add_kernel<<<(B_ * H_ * C_) / 256, 256>>>(out);
}

// round 12
// speedup vs baseline: 1.1781x; 1.0275x over previous
#include <cuda_runtime.h>
#include <math.h>

// Fixed shapes per reference
#define N_PTS 262144
#define B_ 4
#define T_ 4
#define P_ 512
#define R_ 256
#define C_ 64
#define H_ 512
#define W_ 512
#define HW_ (H_ * W_)
#define RC_ (R_ * C_)
#define PRC_ (P_ * RC_)

#define COPY_BLOCKS 16384
#define SCATTER_BLOCKS (N_PTS / 16)       // 16384: 16 points per 256-thr block
#define SCRATCH_ELEMS (B_ * H_ * T_ * C_) // 524288 floats (2MB, L2-resident)

// Privatized accumulator [b][y][t][c] (channel-contiguous -> coalesced REDs).
// BSS zero-init; epilogue re-zeros after consuming (invariant across replays).
__device__ float g_scratch[SCRATCH_ELEMS];

__device__ __forceinline__ void red_add_v4(float* p, float4 v) {
    asm volatile("red.global.add.v4.f32 [%0], {%1,%2,%3,%4};"
                 :: "l"(p), "f"(v.x), "f"(v.y), "f"(v.z), "f"(v.w)
                 : "memory");
}

// Streaming 32B copy with L2 evict_first on BOTH sides (ptxas requires
// .v4.b64/.v8.b32 width for the L2 policy modifier on sm_103a). The 512MB
// copy stream has zero reuse; keeping it out of L2 leaves the cache for the
// pview gather working set (~21% duplicate cell-reads -> L2 hits).
__device__ __forceinline__ ulonglong4 ld_stream32(const ulonglong4* p) {
    ulonglong4 v;
    asm volatile("ld.global.nc.L2::evict_first.v4.b64 {%0,%1,%2,%3}, [%4];"
                 : "=l"(v.x), "=l"(v.y), "=l"(v.z), "=l"(v.w) : "l"(p));
    return v;
}
__device__ __forceinline__ void st_stream32(ulonglong4* p, ulonglong4 v) {
    asm volatile("st.global.L2::evict_first.v4.b64 [%0], {%1,%2,%3,%4};"
                 :: "l"(p), "l"(v.x), "l"(v.y), "l"(v.z), "l"(v.w)
                 : "memory");
}

// One fused kernel, roles interleaved by blockIdx PARITY so every resident
// wave contains both streaming (BW-saturating) and gather (latency-bound)
// blocks — no sequential phases.
__global__ void __launch_bounds__(256) pp_fused_kernel(
    const int4*  __restrict__ coords,
    const float* __restrict__ pview,
    const ulonglong4* __restrict__ spatial32,
    ulonglong4* __restrict__ out32)
{
    const int tid = threadIdx.x;

    if ((blockIdx.x & 1) == 0) {
        // ---- copy path: 256MB out = spatial in 32B chunks, L2-bypassing ----
        // 8388608 chunks total = 16384 blocks * 256 threads * 2 iters (exact).
        int idx = (blockIdx.x >> 1) * 256 + tid;
        const int stride = COPY_BLOCKS * 256;          // 4194304
        #pragma unroll
        for (int i = 0; i < 2; i++) {
            st_stream32(out32 + idx, ld_stream32(spatial32 + idx));
            idx += stride;
        }
        return;
    }

    // ---- scatter path: 16 lanes per point, float4 per lane ----
    const int warp   = tid >> 5;
    const int half   = (tid >> 4) & 1;
    const int lane16 = tid & 15;
    const int pt = (blockIdx.x >> 1) * 16 + warp * 2 + half;

    int4 c = coords[pt];
    const int b = c.x, t = c.y, yy = c.z, xx = c.w;

    // Replicate reference f32 math exactly (no FMA contraction) so the
    // xf==0 special case matches bit-for-bit.
    float yf = __fadd_rn(__fmul_rn((float)yy, 0.2f), -51.2f);
    float xf = __fadd_rn(__fmul_rn((float)xx, 0.2f), -51.2f);

    float r = sqrtf(__fadd_rn(__fmul_rn(xf, xf), __fmul_rn(yf, yf)));
    float psi;
    if (xf == 0.0f && yf >= 0.0f) {
        psi = 1.57079632679489662f;       // pi/2
    } else {
        psi = atan2f(yf, xf);
    }

    float r_idx = __fdiv_rn(r, 0.3f);
    float p_idx = __fdiv_rn(__fadd_rn(psi, 3.14159265358979323846f),
                            0.012566370614359172f);

    int r0i = (int)floorf(r_idx);
    int p0i = (int)floorf(p_idx);
    // t frac is exactly 0 (integer cast to float) -> t+1 corner weight == 0.

    const float fr = r_idx - (float)r0i;
    const float fp = p_idx - (float)p0i;

    const int r0 = r0i * C_;
    const int r1 = min(r0i + 1, R_ - 1) * C_;
    const int p0 = p0i * RC_;
    const int p1 = min(p0i + 1, P_ - 1) * RC_;

    const float* base = pview + (b * T_ + t) * PRC_ + 4 * lane16;

    float4 v00 = *(const float4*)(base + p0 + r0);
    float4 v01 = *(const float4*)(base + p0 + r1);
    float4 v10 = *(const float4*)(base + p1 + r0);
    float4 v11 = *(const float4*)(base + p1 + r1);

    const float wr0 = 1.0f - fr, wr1 = fr;
    const float wp0 = 1.0f - fp, wp1 = fp;

    float4 acc;
    acc.x = wp0 * (wr0 * v00.x + wr1 * v01.x) + wp1 * (wr0 * v10.x + wr1 * v11.x);
    acc.y = wp0 * (wr0 * v00.y + wr1 * v01.y) + wp1 * (wr0 * v10.y + wr1 * v11.y);
    acc.z = wp0 * (wr0 * v00.z + wr1 * v01.z) + wp1 * (wr0 * v10.z + wr1 * v11.z);
    acc.w = wp0 * (wr0 * v00.w + wr1 * v01.w) + wp1 * (wr0 * v10.w + wr1 * v11.w);

    // Coalesced fire-and-forget v4 reduction into the 2MB L2-resident scratch.
    float* dst = g_scratch + ((b * H_ + yy) * T_ + t) * C_ + 4 * lane16;
    red_add_v4(dst, acc);
}

// Epilogue: one thread per (b, y, c) handles all 4 t values.
//  - scratch reads are L2-hot (just written by the scatter reds)
//  - scratch is zeroed back in place (keeps the no-memset invariant)
//  - out update is fire-and-forget red.v4 (no dependent DRAM read)
__global__ void __launch_bounds__(256) pp_add_kernel(float* __restrict__ out)
{
    const int idx = blockIdx.x * 256 + threadIdx.x;  // (b, y, c) flat
    const int ch = idx & (C_ - 1);
    const int y  = (idx >> 6) & (H_ - 1);
    const int b  = idx >> 15;

    const int sbase = ((b * H_ + y) * T_) * C_ + ch;   // t stride = C_
    float v0 = g_scratch[sbase];
    float v1 = g_scratch[sbase + C_];
    float v2 = g_scratch[sbase + 2 * C_];
    float v3 = g_scratch[sbase + 3 * C_];

    g_scratch[sbase]          = 0.0f;
    g_scratch[sbase + C_]     = 0.0f;
    g_scratch[sbase + 2 * C_] = 0.0f;
    g_scratch[sbase + 3 * C_] = 0.0f;

    float4 v = make_float4(v0, v1, v2, v3);
    // out[b][ch][y][0..3] — 16B-aligned (base is a multiple of 512 floats)
    red_add_v4(out + b * (C_ * HW_) + ch * HW_ + y * W_, v);
}

extern "C" void kernel_launch(void* const* d_in, const int* in_sizes, int n_in,
                              void* d_out, int out_size) {
    const int*   coords  = (const int*)d_in[0];   // voxel_coords [N,4] int32
    const float* pview   = (const float*)d_in[1]; // [B,T,P,R,C] f32
    const float* spatial = (const float*)d_in[2]; // [B,C,H,W] f32
    float* out = (float*)d_out;

    pp_fused_kernel<<<COPY_BLOCKS + SCATTER_BLOCKS, 256>>>(
        (const int4*)coords, pview, (const ulonglong4*)spatial, (ulonglong4*)out);

    pp_add_kernel<<<(B_ * H_ * C_) / 256, 256>>>(out);
}